// round 5
// baseline (speedup 1.0000x reference)
#include <cuda_runtime.h>
#include <math.h>

#define J    23
#define TPB  256
#define VPB  1024           // vertices per block
#define PI_F 3.14159265358979323846f

__constant__ int cPAR[J] = {-1,0,1,1,3,4,5,4,7,4,9,1,11,12,13,12,15,12,17,0,19,0,21};

// Dynamic smem layout (floats):
//   [0, 23552)        s_sk   (1024*23)
//   [23552, 26624)    s_res  (1024*3)  -- FK scratch (Tl 288 + G 288) lives here pre-sync
//   [26624, 26900)    s_A    (69 float4)
//   [26900, 26904)    s_c
#define SMEM_FLOATS 26904
#define SMEM_BYTES  (SMEM_FLOATS * 4)

__global__ void __launch_bounds__(TPB, 2) fused_lbs_kernel(
    const float* __restrict__ vt,
    const float* __restrict__ sk,
    const float* __restrict__ la,
    const float* __restrict__ jr,
    const float* __restrict__ p0, const float* __restrict__ p1,
    const float* __restrict__ p2, const float* __restrict__ p3,
    const float* __restrict__ p4, const float* __restrict__ p5,
    const float* __restrict__ p12, const float* __restrict__ p13,
    const float* __restrict__ disp, const float* __restrict__ scale,
    const float* __restrict__ loc,
    float* __restrict__ out, int V, int B)
{
    extern __shared__ float smem[];
    float*  s_sk  = smem;
    float*  s_res = smem + 23552;
    float4* s_A4  = (float4*)(smem + 26624);
    float*  s_c   = smem + 26900;

    const int tid  = threadIdx.x;
    const int blk  = blockIdx.x;
    const long v0  = (long)blk * VPB;
    const int nv   = (V - (int)v0 < VPB) ? (V - (int)v0) : VPB;   // multiple of 4
    const int nq   = nv >> 2;
    const long V3  = 3L * (long)V;
    const long offLa = (long)B * V3 + 142;

    // ===== Phase A (warp 0): FK -> s_A4, s_c.  Phase B (warps 1-7): coop fill s_sk =====
    if (tid >= 32) {
        const float4* g4 = (const float4*)(sk + v0 * 23);
        float4* d4 = (float4*)s_sk;
        const int nS = (nv * 23) >> 2;
        for (int i = tid - 32; i < nS; i += (TPB - 32)) d4[i] = __ldcs(g4 + i);
    } else {
        float* s_Tl = s_res;          // 288 floats
        float* s_G  = s_res + 288;    // 288 floats

        if (tid == 31) {
            float cst = 0.0035f * scale[0];
            s_c[0] = cst;
            s_c[1] = loc[0] + 0.1f * tanhf(disp[0]);
            s_c[2] = loc[1] + 0.1f * tanhf(disp[1]);
            s_c[3] = loc[2] + 0.1f * tanhf(disp[2]);
        }

        float px = 0.f, py = 0.f, pz = 0.f;
        if (tid < J) {
            float fac = 0.f, sy = 1.f, sz = 1.f;
            const float* pp = p0;
            bool has = true;
            switch (tid) {
                case 0:  fac = PI_F / 2.f; pp = p0;  break;
                case 1:  fac = PI_F / 4.f; pp = p1;  break;
                case 2:  fac = PI_F / 9.f; pp = p2;  break;
                case 3:  fac = PI_F / 3.f; pp = p3;  break;
                case 4:  fac = PI_F / 3.f; pp = p4;  break;
                case 5:  fac = PI_F / 3.f; pp = p5;  break;
                case 11: fac = PI_F / 3.f; pp = p3;  sy = -1.f; sz = -1.f; break;
                case 12: fac = PI_F / 3.f; pp = p12; break;
                case 13: fac = PI_F / 3.f; pp = p13; break;
                default: has = false;
            }
            if (has) {
                px = fac * tanhf(pp[0]);
                py = sy * fac * tanhf(pp[1]);
                pz = sz * fac * tanhf(pp[2]);
            }
            float ang = sqrtf(px * px + py * py + pz * pz + 1e-12f);
            float inv = 1.f / ang;
            float x = px * inv, y = py * inv, z = pz * inv;
            float s = sinf(ang), c = cosf(ang), t = 1.f - c;
            float* T = &s_Tl[tid * 12];
            T[0] = 1.f + t * (-(z * z) - (y * y));
            T[1] = -s * z + t * (x * y);
            T[2] =  s * y + t * (x * z);
            T[4] =  s * z + t * (x * y);
            T[5] = 1.f + t * (-(z * z) - (x * x));
            T[6] = -s * x + t * (y * z);
            T[8] = -s * y + t * (x * z);
            T[9] =  s * x + t * (y * z);
            T[10] = 1.f + t * (-(y * y) - (x * x));

            int par = cPAR[tid];
            float jx = jr[3 * tid], jy = jr[3 * tid + 1], jz = jr[3 * tid + 2];
            if (par >= 0) { jx -= jr[3 * par]; jy -= jr[3 * par + 1]; jz -= jr[3 * par + 2]; }
            T[3] = jx; T[7] = jy; T[11] = jz;
        }
        __syncwarp();

        if (tid < 12) s_G[tid] = s_Tl[tid];
        __syncwarp();
        #pragma unroll
        for (int j = 1; j < J; j++) {
            const int p = cPAR[j];
            if (tid < 12) {
                const int r = tid >> 2, c = tid & 3;
                const float* gp = &s_G[p * 12 + r * 4];
                const float* tl = &s_Tl[j * 12];
                float v = gp[0] * tl[0 * 4 + c]
                        + gp[1] * tl[1 * 4 + c]
                        + gp[2] * tl[2 * 4 + c];
                if (c == 3) v += gp[3];
                s_G[j * 12 + tid] = v;
            }
            __syncwarp();
        }

        if (tid < J) {
            const float* g = &s_G[tid * 12];
            float jx = jr[3 * tid], jy = jr[3 * tid + 1], jz = jr[3 * tid + 2];
            float tcx = g[0] * jx + g[1] * jy + g[2] * jz;
            float tcy = g[4] * jx + g[5] * jy + g[6] * jz;
            float tcz = g[8] * jx + g[9] * jy + g[10] * jz;
            s_A4[tid * 3 + 0] = make_float4(g[0], g[1], g[2],  g[3]  - tcx);
            s_A4[tid * 3 + 1] = make_float4(g[4], g[5], g[6],  g[7]  - tcy);
            s_A4[tid * 3 + 2] = make_float4(g[8], g[9], g[10], g[11] - tcz);
        }
        __syncwarp();

        // small outputs from block 0
        if (blk == 0 && tid < J) {
            const long base = (long)B * V3;
            out[base + 3 * tid + 0] = px;
            out[base + 3 * tid + 1] = py;
            out[base + 3 * tid + 2] = pz;
            float cst = s_c[0];
            out[base + 69 + 3 * tid + 0] = fmaf(cst, s_G[tid * 12 + 3],  s_c[1]);
            out[base + 69 + 3 * tid + 1] = fmaf(cst, s_G[tid * 12 + 7],  s_c[2]);
            out[base + 69 + 3 * tid + 2] = fmaf(cst, s_G[tid * 12 + 11], s_c[3]);
        }
        if (blk == 0 && tid == 31) {
            const long base = (long)B * V3;
            out[base + 138] = scale[0];
            out[base + 139] = disp[0];
            out[base + 140] = disp[1];
            out[base + 141] = disp[2];
        }
    }

    // ===== per-thread vt/la loads + la passthrough + vh (all threads with a quad) =====
    float vh[4][3];
    if (tid < nq) {
        const long q0 = v0 + 4L * tid;
        const float4* vt4 = (const float4*)(vt + q0 * 3);
        const float4* la4 = (const float4*)(la + q0 * 3);
        float4 vq0 = __ldcs(vt4 + 0), vq1 = __ldcs(vt4 + 1), vq2 = __ldcs(vt4 + 2);
        float4 lq0 = __ldcs(la4 + 0), lq1 = __ldcs(la4 + 1), lq2 = __ldcs(la4 + 2);

        // la passthrough (offset ≡ 2 mod 4 -> float2 stores)
        float2* gl2 = (float2*)(out + offLa + q0 * 3);
        __stcs(gl2 + 0, make_float2(lq0.x, lq0.y));
        __stcs(gl2 + 1, make_float2(lq0.z, lq0.w));
        __stcs(gl2 + 2, make_float2(lq1.x, lq1.y));
        __stcs(gl2 + 3, make_float2(lq1.z, lq1.w));
        __stcs(gl2 + 4, make_float2(lq2.x, lq2.y));
        __stcs(gl2 + 5, make_float2(lq2.z, lq2.w));

        const float* vf = &vq0.x;   // 12 contiguous via structs below
        float vv[12] = {vq0.x,vq0.y,vq0.z,vq0.w, vq1.x,vq1.y,vq1.z,vq1.w, vq2.x,vq2.y,vq2.z,vq2.w};
        float ll[12] = {lq0.x,lq0.y,lq0.z,lq0.w, lq1.x,lq1.y,lq1.z,lq1.w, lq2.x,lq2.y,lq2.z,lq2.w};
        (void)vf;
        #pragma unroll
        for (int a = 0; a < 4; a++)
            #pragma unroll
            for (int k = 0; k < 3; k++)
                vh[a][k] = vv[3 * a + k] + 0.1f * tanhf(ll[3 * a + k]);
    }

    __syncthreads();

    // ===== compute: T = sum_j w_j A_j for 4 vertices; epilogue; stage into s_res =====
    if (tid < nq) {
        float4 T0[4], T1[4], T2[4];
        #pragma unroll
        for (int a = 0; a < 4; a++) {
            T0[a] = make_float4(0.f, 0.f, 0.f, 0.f);
            T1[a] = make_float4(0.f, 0.f, 0.f, 0.f);
            T2[a] = make_float4(0.f, 0.f, 0.f, 0.f);
        }

        const float* wbase = &s_sk[92 * tid];
        #pragma unroll
        for (int j = 0; j < J; j++) {
            const float4 a0 = s_A4[3 * j + 0];
            const float4 a1 = s_A4[3 * j + 1];
            const float4 a2 = s_A4[3 * j + 2];
            #pragma unroll
            for (int a = 0; a < 4; a++) {
                const float w = wbase[23 * a + j];
                T0[a].x = fmaf(w, a0.x, T0[a].x); T0[a].y = fmaf(w, a0.y, T0[a].y);
                T0[a].z = fmaf(w, a0.z, T0[a].z); T0[a].w = fmaf(w, a0.w, T0[a].w);
                T1[a].x = fmaf(w, a1.x, T1[a].x); T1[a].y = fmaf(w, a1.y, T1[a].y);
                T1[a].z = fmaf(w, a1.z, T1[a].z); T1[a].w = fmaf(w, a1.w, T1[a].w);
                T2[a].x = fmaf(w, a2.x, T2[a].x); T2[a].y = fmaf(w, a2.y, T2[a].y);
                T2[a].z = fmaf(w, a2.z, T2[a].z); T2[a].w = fmaf(w, a2.w, T2[a].w);
            }
        }

        const float c = s_c[0];
        float res[12];
        #pragma unroll
        for (int a = 0; a < 4; a++) {
            float x = fmaf(T0[a].x, vh[a][0], fmaf(T0[a].y, vh[a][1], fmaf(T0[a].z, vh[a][2], T0[a].w)));
            float y = fmaf(T1[a].x, vh[a][0], fmaf(T1[a].y, vh[a][1], fmaf(T1[a].z, vh[a][2], T1[a].w)));
            float z = fmaf(T2[a].x, vh[a][0], fmaf(T2[a].y, vh[a][1], fmaf(T2[a].z, vh[a][2], T2[a].w)));
            res[3 * a + 0] = fmaf(c, x, s_c[1]);
            res[3 * a + 1] = fmaf(c, y, s_c[2]);
            res[3 * a + 2] = fmaf(c, z, s_c[3]);
        }

        float4* r4 = (float4*)(s_res + 12 * tid);
        r4[0] = make_float4(res[0], res[1], res[2],  res[3]);
        r4[1] = make_float4(res[4], res[5], res[6],  res[7]);
        r4[2] = make_float4(res[8], res[9], res[10], res[11]);
    }

    __syncthreads();

    // ===== coalesced batch stores =====
    {
        const int n4 = (nv * 3) >> 2;
        const float4* r4 = (const float4*)s_res;
        for (int b = 0; b < B; b++) {
            float4* go = (float4*)(out + (long)b * V3 + v0 * 3);
            for (int i = tid; i < n4; i += TPB) __stcs(go + i, r4[i]);
        }
    }
}

extern "C" void kernel_launch(void* const* d_in, const int* in_sizes, int n_in,
                              void* d_out, int out_size)
{
    const float* vt    = (const float*)d_in[0];
    const float* sk    = (const float*)d_in[1];
    const float* jr    = (const float*)d_in[2];
    const float* p0    = (const float*)d_in[3];
    const float* p1    = (const float*)d_in[4];
    const float* p2    = (const float*)d_in[5];
    const float* p3    = (const float*)d_in[6];
    const float* p4    = (const float*)d_in[7];
    const float* p5    = (const float*)d_in[8];
    const float* p12   = (const float*)d_in[9];
    const float* p13   = (const float*)d_in[10];
    const float* la    = (const float*)d_in[11];
    const float* disp  = (const float*)d_in[12];
    const float* scale = (const float*)d_in[13];
    const float* loc   = (const float*)d_in[14];
    float* out = (float*)d_out;

    int V = in_sizes[0] / 3;
    long fixed = 69L + 69L + 1L + 3L + 3L * (long)V;
    int B = (int)(((long)out_size - fixed) / (3L * (long)V));

    static int smem_set = 0;
    if (!smem_set) {
        cudaFuncSetAttribute(fused_lbs_kernel,
                             cudaFuncAttributeMaxDynamicSharedMemorySize, SMEM_BYTES);
        smem_set = 1;
    }

    int blocks = (V + VPB - 1) / VPB;
    fused_lbs_kernel<<<blocks, TPB, SMEM_BYTES>>>(
        vt, sk, la, jr, p0, p1, p2, p3, p4, p5, p12, p13,
        disp, scale, loc, out, V, B);
}